// round 3
// baseline (speedup 1.0000x reference)
#include <cuda_runtime.h>

// Guided attention loss: out = sum_{b,i,j} aln[b,i,j] * w(b,i,j) / B
// w = 1 - exp(-(i - j/Ti*To)^2 / (2*sigma^2)), zero for i>=To or j>=Ti.
//
// block = i (0..1999), thread = j-chunk (128 float4), batch b = inner loop.
// Double-buffered batch groups: 4 predicated streaming LDG.128 for group g+1
// issued before computing group g -> sustained MLP>=4 per warp.
// Single kernel: last-finishing block finalizes (sum/B -> d_out) and resets
// the device scratch so the launch is graph-replay deterministic.

#define B_DIM   64
#define T_OUT   2000
#define T_IN    512
#define NEG_INV2S2 (-3.125f)   // -1/(2*0.4^2)

__device__ double       g_acc;       // zero-init at load; reset by last block
__device__ unsigned int g_cnt;

__device__ __forceinline__ float4 ldcs4(const float4* p) {
    return __ldcs(p);   // streaming: evict-first, no L2 retention
}

__global__ __launch_bounds__(128) void gal_main(
    const float4* __restrict__ aln,
    const int*    __restrict__ ilen,
    const int*    __restrict__ olen,
    float*        __restrict__ out)
{
    __shared__ float sTo[B_DIM];
    __shared__ float sTi[B_DIM];
    __shared__ float sR [B_DIM];

    const int t = threadIdx.x;     // 0..127
    if (t < B_DIM)            sTo[t]         = (float)olen[t];
    else if (t < 2 * B_DIM)   sTi[t - B_DIM] = (float)ilen[t - B_DIM];
    __syncthreads();
    if (t < B_DIM) sR[t] = __fdividef(sTo[t], sTi[t]);
    __syncthreads();

    const int   i  = blockIdx.x;
    const float fi = (float)i;
    const float jb = (float)(t * 4);
    float acc = 0.0f;

    const float4* p0 = aln + ((size_t)i * (T_IN / 4)) + t;
    const size_t  bstride = (size_t)T_OUT * (T_IN / 4);

    float4 cur[4];
    bool   pcur[4];

    // prime group 0
    #pragma unroll
    for (int k = 0; k < 4; ++k) {
        pcur[k] = (fi < sTo[k]) & (jb < sTi[k]);
        cur[k] = make_float4(0.f, 0.f, 0.f, 0.f);
        if (pcur[k]) cur[k] = ldcs4(p0 + (size_t)k * bstride);
    }

    #pragma unroll 1
    for (int it = 0; it < B_DIM; it += 4) {
        float4 nxt[4];
        bool   pnxt[4];
        // ---- prefetch next group (front-batched, independent) ----
        if (it + 4 < B_DIM) {
            #pragma unroll
            for (int k = 0; k < 4; ++k) {
                const int b = it + 4 + k;
                pnxt[k] = (fi < sTo[b]) & (jb < sTi[b]);
                nxt[k] = make_float4(0.f, 0.f, 0.f, 0.f);
                if (pnxt[k]) nxt[k] = ldcs4(p0 + (size_t)b * bstride);
            }
        }
        // ---- compute current group ----
        #pragma unroll
        for (int k = 0; k < 4; ++k) {
            if (!pcur[k]) continue;
            const int   b   = it + k;
            const float Tif = sTi[b];
            const float r   = sR[b];
            const float av[4] = {cur[k].x, cur[k].y, cur[k].z, cur[k].w};
            float d = fi - jb * r;           // d_{kk+1} = d_kk - r
            #pragma unroll
            for (int kk = 0; kk < 4; ++kk) {
                if (jb + (float)kk < Tif) {
                    const float e = __expf(d * d * NEG_INV2S2);
                    acc += av[kk] - av[kk] * e;   // a*(1-e)
                }
                d -= r;
            }
        }
        if (it + 4 < B_DIM) {
            #pragma unroll
            for (int k = 0; k < 4; ++k) { cur[k] = nxt[k]; pcur[k] = pnxt[k]; }
        }
    }

    // block reduce
    #pragma unroll
    for (int off = 16; off > 0; off >>= 1)
        acc += __shfl_down_sync(0xFFFFFFFFu, acc, off);

    __shared__ float ws[4];
    if ((t & 31) == 0) ws[t >> 5] = acc;
    __syncthreads();

    if (t == 0) {
        atomicAdd(&g_acc, (double)(ws[0] + ws[1] + ws[2] + ws[3]));
        __threadfence();
        const unsigned done = atomicAdd(&g_cnt, 1u);
        if (done == (unsigned)(gridDim.x - 1)) {
            // last block: all g_acc contributions are visible
            const double total = *((volatile double*)&g_acc);
            out[0] = (float)(total / (double)B_DIM);
            // reset scratch for the next graph replay
            *((volatile double*)&g_acc) = 0.0;
            __threadfence();
            *((volatile unsigned*)&g_cnt) = 0u;
        }
    }
}

extern "C" void kernel_launch(void* const* d_in, const int* in_sizes, int n_in,
                              void* d_out, int out_size)
{
    const float4* aln  = (const float4*)d_in[0];
    const int*    ilen = (const int*)d_in[1];
    const int*    olen = (const int*)d_in[2];

    gal_main<<<T_OUT, 128>>>(aln, ilen, olen, (float*)d_out);
}

// round 4
// speedup vs baseline: 1.7438x; 1.7438x over previous
#include <cuda_runtime.h>

// Guided attention loss: out = sum_{b,i,j} aln[b,i,j] * w(b,i,j) / B
// w = 1 - exp(-(i - j*To/Ti)^2 / (2*0.4^2)), zero for i>=To or j>=Ti.
//
// Split: w == 1.0f exactly (fp32) outside the band |i - j*To/Ti| <= ~2.4.
//   loss = sum_valid(a)  -  sum_band(a * exp(...))
// Main path is a pure masked streaming sum (no exp). Band (<=4 j per row)
// handled by threads 0..63 per block. Finalize fused via last-block-done.

#define B_DIM   64
#define T_OUT   2000
#define T_IN    512
#define NEG_INV2S2 (-3.125f)   // -1/(2*0.4^2)
#define BAND    3.0f           // |d|>2.36 -> 1-e == 1.0f; 3.0 for margin

__device__ double       g_acc;   // zero-init at load; reset by last block
__device__ unsigned int g_cnt;

__global__ __launch_bounds__(128) void gal_main(
    const float4* __restrict__ aln,
    const int*    __restrict__ ilen,
    const int*    __restrict__ olen,
    float*        __restrict__ out)
{
    __shared__ int   siTo[B_DIM], siTi[B_DIM];
    __shared__ float sR[B_DIM], sInvR[B_DIM];

    const int t = threadIdx.x;             // 0..127
    if (t < B_DIM)          siTo[t]         = olen[t];
    else if (t < 2 * B_DIM) siTi[t - B_DIM] = ilen[t - B_DIM];
    __syncthreads();
    if (t < B_DIM) {
        const float To = (float)siTo[t], Ti = (float)siTi[t];
        sR[t]    = __fdividef(To, Ti);
        sInvR[t] = __fdividef(Ti, To);
    }
    __syncthreads();

    const int   i   = blockIdx.x;
    const float fi  = (float)i;
    const int   jb4 = t * 4;               // first j this thread owns
    float acc = 0.0f;

    // ---- band correction first (scattered loads overlap main-loop latency) ----
    if (t < B_DIM) {
        const int To = siTo[t], Ti = siTi[t];
        if (i < To) {
            const float r    = sR[t];
            const float invr = sInvR[t];
            int jlo = (int)ceilf((fi - BAND) * invr);
            if (jlo < 0) jlo = 0;
            int jhi = (int)floorf((fi + BAND) * invr);
            if (jhi > Ti - 1) jhi = Ti - 1;
            const float* row = (const float*)aln + ((size_t)t * T_OUT + i) * T_IN;

            float av[5];
            #pragma unroll
            for (int u = 0; u < 5; ++u) {          // independent loads
                const int j = jlo + u;
                av[u] = (j <= jhi) ? __ldg(row + j) : 0.0f;
            }
            #pragma unroll
            for (int u = 0; u < 5; ++u) {
                const float d = fi - (float)(jlo + u) * r;
                acc -= av[u] * __expf(d * d * NEG_INV2S2);
            }
            for (int j = jlo + 5; j <= jhi; ++j) { // safety, never runs for these shapes
                const float d = fi - (float)j * r;
                acc -= __ldg(row + j) * __expf(d * d * NEG_INV2S2);
            }
        }
    }

    // ---- main masked streaming sum: w treated as 1 everywhere valid ----
    const float4* p0 = aln + ((size_t)i * (T_IN / 4)) + t;
    const size_t  bstride = (size_t)T_OUT * (T_IN / 4);

    #pragma unroll 1
    for (int it = 0; it < B_DIM; it += 4) {
        float4 a[4];
        int    m[4];                        // valid element count in chunk (<=0: none)
        #pragma unroll
        for (int k = 0; k < 4; ++k) {       // front-batched independent loads, MLP=4
            const int b = it + k;
            m[k] = (i < siTo[b]) ? (siTi[b] - jb4) : 0;
            a[k] = make_float4(0.f, 0.f, 0.f, 0.f);
            if (m[k] > 0) a[k] = __ldcs(p0 + (size_t)b * bstride);
        }
        #pragma unroll
        for (int k = 0; k < 4; ++k) {
            if (m[k] >= 4) {                // common path: whole chunk valid
                acc += (a[k].x + a[k].y) + (a[k].z + a[k].w);
            } else if (m[k] > 0) {          // boundary chunk (1 thread per row)
                acc += a[k].x;
                if (m[k] > 1) acc += a[k].y;
                if (m[k] > 2) acc += a[k].z;
            }
        }
    }

    // ---- block reduce ----
    #pragma unroll
    for (int off = 16; off > 0; off >>= 1)
        acc += __shfl_down_sync(0xFFFFFFFFu, acc, off);

    __shared__ float ws[4];
    if ((t & 31) == 0) ws[t >> 5] = acc;
    __syncthreads();

    if (t == 0) {
        atomicAdd(&g_acc, (double)(ws[0] + ws[1] + ws[2] + ws[3]));
        __threadfence();
        const unsigned done = atomicAdd(&g_cnt, 1u);
        if (done == (unsigned)(gridDim.x - 1)) {
            const double total = *((volatile double*)&g_acc);
            out[0] = (float)(total / (double)B_DIM);
            *((volatile double*)&g_acc) = 0.0;   // reset for next graph replay
            __threadfence();
            *((volatile unsigned*)&g_cnt) = 0u;
        }
    }
}

extern "C" void kernel_launch(void* const* d_in, const int* in_sizes, int n_in,
                              void* d_out, int out_size)
{
    const float4* aln  = (const float4*)d_in[0];
    const int*    ilen = (const int*)d_in[1];
    const int*    olen = (const int*)d_in[2];

    gal_main<<<T_OUT, 128>>>(aln, ilen, olen, (float*)d_out);
}